// round 1
// baseline (speedup 1.0000x reference)
#include <cuda_runtime.h>

#define EPC 8  // elements per CTA

__global__ __launch_bounds__(256, 2)
void ntc_fused(const int* __restrict__ gI, const int* __restrict__ gJ, const int* __restrict__ gK,
               const float* __restrict__ A, const float* __restrict__ B, const float* __restrict__ C,
               const float* __restrict__ W0, const float* __restrict__ b0,
               const float* __restrict__ W1, const float* __restrict__ b1,
               const float* __restrict__ W2, const float* __restrict__ b2,
               const float* __restrict__ W3, const float* __restrict__ b3,
               const float* __restrict__ FCW, const float* __restrict__ FCB,
               float* __restrict__ out, int n)
{
    // shared scratch (per element, reused across the element loop)
    __shared__ float  s_abc[48];         // a[16] | b[16] | c[16]
    __shared__ float  s_BC[16][16];      // b ⊗ c outer product
    __shared__ float4 s_WA[8][32];       // [P][f] : W0 pre-contracted with a-pair
    __shared__ float  s_y0[8][8][32];    // [t1][tap0][c]  layer0 acts for one q2 cell
    __shared__ float  s_p1[8][8][32];    // [t1][warp][f]  layer1 partials
    __shared__ float  s_y1[8][32];       // [t1][c]
    __shared__ float  s_p2[8][8][32];    // [q2][warp][f]  layer2 partials
    __shared__ float  s_y2[8][32];       // [q2][c]
    __shared__ float  s_p3[8][32];       // [warp][f]      layer3 partials

    const int tid  = threadIdx.x;
    const int lane = tid & 31;
    const int wrp  = tid >> 5;

    // ---- persistent weight registers ----
    // lane f = output channel; warp w = input-channel slice [4w, 4w+4)
    float w0r[8];
#pragma unroll
    for (int t = 0; t < 8; ++t) w0r[t] = W0[lane * 8 + t];

    float w1r[32], w2r[32];  // [c'][tap], c' = 0..3 within slice
#pragma unroll
    for (int cp = 0; cp < 4; ++cp)
#pragma unroll
        for (int t = 0; t < 8; ++t) {
            w1r[cp * 8 + t] = W1[(lane * 32 + 4 * wrp + cp) * 8 + t];
            w2r[cp * 8 + t] = W2[(lane * 32 + 4 * wrp + cp) * 8 + t];
        }
    const float bias0 = b0[lane];
    const float bias1 = b1[lane];
    const float bias2 = b2[lane];
    const float bias3 = b3[lane];

    // warp's (d1,h1,w1) bits: warp id encodes the position-within-cell index t1
    const int wd = (wrp >> 2) & 1, wh = (wrp >> 1) & 1, ww = wrp & 1;

    const int ebase = blockIdx.x * EPC;
    for (int e0 = 0; e0 < EPC; ++e0) {
        const int e = ebase + e0;
        if (e >= n) break;                 // uniform across CTA
        __syncthreads();                   // smem reuse boundary

        // ---- gather a, b, c rows ----
        if (tid < 48) {
            const int which = tid >> 4, idx = tid & 15;
            const int row = (which == 0) ? gI[e] : (which == 1 ? gJ[e] : gK[e]);
            const float* src = (which == 0) ? A : (which == 1 ? B : C);
            s_abc[tid] = src[row * 16 + idx];
        }
        __syncthreads();

        // ---- BC outer product + WA contraction ----
        (&s_BC[0][0])[tid] = s_abc[16 + (tid >> 4)] * s_abc[32 + (tid & 15)];
        {
            const float a0 = s_abc[2 * wrp], a1 = s_abc[2 * wrp + 1];
            // WA[f][P][q] = W0[f,0,q]*a[2P] + W0[f,1,q]*a[2P+1], q = kh*2+kw, P = wrp
            s_WA[wrp][lane] = make_float4(
                fmaf(w0r[0], a0, w0r[4] * a1),
                fmaf(w0r[1], a0, w0r[5] * a1),
                fmaf(w0r[2], a0, w0r[6] * a1),
                fmaf(w0r[3], a0, w0r[7] * a1));
        }
        __syncthreads();

        // ---- depth-first over the 8 layer-2 output cells ----
        for (int q2 = 0; q2 < 8; ++q2) {
            const int D1  = 2 * ((q2 >> 2) & 1) + wd;
            const int H1  = 2 * ((q2 >> 1) & 1) + wh;
            const int Wd1 = 2 * (q2 & 1) + ww;

            // layer0: thread -> (c = lane, t1 = wrp), 8 taps
#pragma unroll
            for (int tap = 0; tap < 8; ++tap) {
                const int P  = 2 * D1 + ((tap >> 2) & 1);
                const int Q  = 2 * H1 + ((tap >> 1) & 1);
                const int Rr = 2 * Wd1 + (tap & 1);
                const float4 wa = s_WA[P][lane];
                const float2 bcA = *(const float2*)&s_BC[2 * Q][2 * Rr];
                const float2 bcB = *(const float2*)&s_BC[2 * Q + 1][2 * Rr];
                float v = bias0;
                v = fmaf(wa.x, bcA.x, v);
                v = fmaf(wa.y, bcA.y, v);
                v = fmaf(wa.z, bcB.x, v);
                v = fmaf(wa.w, bcB.y, v);
                s_y0[wrp][tap][lane] = fmaxf(v, 0.0f);
            }
            __syncthreads();

            // layer1 partials: warp's 4-channel K-slice, all 8 positions t1
#pragma unroll
            for (int t1 = 0; t1 < 8; ++t1) {
                float accA = 0.f, accB = 0.f;
#pragma unroll
                for (int tap = 0; tap < 8; ++tap) {
                    const float4 v = *(const float4*)&s_y0[t1][tap][4 * wrp];
                    accA = fmaf(w1r[tap],      v.x, accA);
                    accB = fmaf(w1r[8 + tap],  v.y, accB);
                    accA = fmaf(w1r[16 + tap], v.z, accA);
                    accB = fmaf(w1r[24 + tap], v.w, accB);
                }
                s_p1[t1][wrp][lane] = accA + accB;
            }
            __syncthreads();

            // reduce partials -> y1 (thread: t1 = wrp, f = lane)
            {
                float s = s_p1[wrp][0][lane];
#pragma unroll
                for (int wi = 1; wi < 8; ++wi) s += s_p1[wrp][wi][lane];
                s_y1[wrp][lane] = fmaxf(s + bias1, 0.0f);
            }
            __syncthreads();

            // layer2 partial for this q2 cell
            {
                float accA = 0.f, accB = 0.f;
#pragma unroll
                for (int t1 = 0; t1 < 8; ++t1) {
                    const float4 v = *(const float4*)&s_y1[t1][4 * wrp];
                    accA = fmaf(w2r[t1],      v.x, accA);
                    accB = fmaf(w2r[8 + t1],  v.y, accB);
                    accA = fmaf(w2r[16 + t1], v.z, accA);
                    accB = fmaf(w2r[24 + t1], v.w, accB);
                }
                s_p2[q2][wrp][lane] = accA + accB;
            }
        }
        __syncthreads();

        // reduce -> y2 (thread: q2 = wrp, c = lane)
        {
            float s = s_p2[wrp][0][lane];
#pragma unroll
            for (int wi = 1; wi < 8; ++wi) s += s_p2[wrp][wi][lane];
            s_y2[wrp][lane] = fmaxf(s + bias2, 0.0f);
        }
        __syncthreads();

        // layer3 partial (W3 via LDG: same addresses every element -> L1-resident)
        {
            float accA = 0.f, accB = 0.f;
#pragma unroll
            for (int q2 = 0; q2 < 8; ++q2) {
                const float4 v = *(const float4*)&s_y2[q2][4 * wrp];
                const float* w3p = &W3[(lane * 32 + 4 * wrp) * 8 + q2];
                accA = fmaf(w3p[0],  v.x, accA);
                accB = fmaf(w3p[8],  v.y, accB);
                accA = fmaf(w3p[16], v.z, accA);
                accB = fmaf(w3p[24], v.w, accB);
            }
            s_p3[wrp][lane] = accA + accB;
        }
        __syncthreads();

        // final reduce + fc + sigmoid (warp 0)
        if (wrp == 0) {
            float s = s_p3[0][lane];
#pragma unroll
            for (int wi = 1; wi < 8; ++wi) s += s_p3[wi][lane];
            const float y3 = fmaxf(s + bias3, 0.0f);
            float v = FCW[lane] * y3;
#pragma unroll
            for (int off = 16; off; off >>= 1)
                v += __shfl_xor_sync(0xffffffffu, v, off);
            if (lane == 0) {
                const float x = v + FCB[0];
                out[e] = 1.0f / (1.0f + __expf(-x));
            }
        }
    }
}

extern "C" void kernel_launch(void* const* d_in, const int* in_sizes, int n_in,
                              void* d_out, int out_size) {
    const int*   gI  = (const int*)d_in[0];
    const int*   gJ  = (const int*)d_in[1];
    const int*   gK  = (const int*)d_in[2];
    const float* A   = (const float*)d_in[3];
    const float* B   = (const float*)d_in[4];
    const float* C   = (const float*)d_in[5];
    const float* W0  = (const float*)d_in[6];
    const float* b0  = (const float*)d_in[7];
    const float* W1  = (const float*)d_in[8];
    const float* b1  = (const float*)d_in[9];
    const float* W2  = (const float*)d_in[10];
    const float* b2  = (const float*)d_in[11];
    const float* W3  = (const float*)d_in[12];
    const float* b3  = (const float*)d_in[13];
    const float* FCW = (const float*)d_in[14];
    const float* FCB = (const float*)d_in[15];

    const int n = in_sizes[0];
    const int grid = (n + EPC - 1) / EPC;
    ntc_fused<<<grid, 256>>>(gI, gJ, gK, A, B, C, W0, b0, W1, b1, W2, b2,
                             W3, b3, FCW, FCB, (float*)d_out, n);
}

// round 2
// speedup vs baseline: 1.6553x; 1.6553x over previous
#include <cuda_runtime.h>

#define EPC 8
#define SMF 8448   // floats of shared: max(stage buffer 8446, persistent 8256)

// Persistent smem layout (float offsets); the weight-stage buffer overlays all of it
#define S_ABC 0      // 48
#define S_BC  64     // 16x16
#define S_WA  320    // 8x32 float4 (1024 floats)
#define S_Y0  1344   // [t1][tap][c] 8*8*32
#define S_P1  3392   // [t1][w][f]
#define S_Y1  5440   // [t1][c]
#define S_P2  5696   // [q2][w][f]
#define S_Y2  7744   // [q2][c]
#define S_P3  8000   // [w][f]

// Stage Wsrc (layout [f=32][c=32][t=8]) into transposed padded smem, fill per-thread regs
// wreg[cp*8+t] = Wsrc[(lane*32 + 4*wrp + cp)*8 + t]
#define STAGE(Wsrc, wreg) do {                                              \
    __syncthreads();                                                        \
    _Pragma("unroll")                                                       \
    for (int r = 0; r < 8; ++r) {                                           \
        int i4 = tid + 256 * r;                                             \
        float4 v = ((const float4*)(Wsrc))[i4];                             \
        int f = i4 >> 6, rem = i4 & 63, c = rem >> 1, tb = (rem & 1) * 4;   \
        sm[((tb + 0) * 32 + c) * 33 + f] = v.x;                             \
        sm[((tb + 1) * 32 + c) * 33 + f] = v.y;                             \
        sm[((tb + 2) * 32 + c) * 33 + f] = v.z;                             \
        sm[((tb + 3) * 32 + c) * 33 + f] = v.w;                             \
    }                                                                       \
    __syncthreads();                                                        \
    _Pragma("unroll")                                                       \
    for (int cp = 0; cp < 4; ++cp)                                          \
        _Pragma("unroll")                                                   \
        for (int t = 0; t < 8; ++t)                                         \
            wreg[cp * 8 + t] = sm[(t * 32 + 4 * wrp + cp) * 33 + lane];     \
} while (0)

__global__ __launch_bounds__(256, 2)
void ntc_fused(const int* __restrict__ gI, const int* __restrict__ gJ, const int* __restrict__ gK,
               const float* __restrict__ A, const float* __restrict__ Bm, const float* __restrict__ Cm,
               const float* __restrict__ W0, const float* __restrict__ b0,
               const float* __restrict__ W1, const float* __restrict__ b1,
               const float* __restrict__ W2, const float* __restrict__ b2,
               const float* __restrict__ W3, const float* __restrict__ b3,
               const float* __restrict__ FCW, const float* __restrict__ FCB,
               float* __restrict__ out, int n)
{
    __shared__ alignas(16) float sm[SMF];

    const int tid  = threadIdx.x;
    const int lane = tid & 31;
    const int wrp  = tid >> 5;

    // ---- CTA prologue: all conv weights into registers via staged transpose ----
    float w1r[32], w2r[32], w3r[32];
    STAGE(W1, w1r);
    STAGE(W2, w2r);
    STAGE(W3, w3r);

    float w0r[8];
#pragma unroll
    for (int t = 0; t < 8; ++t) w0r[t] = W0[lane * 8 + t];
    const float bias0 = b0[lane], bias1 = b1[lane], bias2 = b2[lane], bias3 = b3[lane];
    const float fcw = FCW[lane], fcb = FCB[0];

    const int wd = (wrp >> 2) & 1, wh = (wrp >> 1) & 1, ww = wrp & 1;

    const int ebase = blockIdx.x * EPC;
    for (int e0 = 0; e0 < EPC; ++e0) {
        const int e = ebase + e0;
        if (e >= n) break;             // uniform across CTA
        __syncthreads();               // smem reuse boundary (also covers prologue)

        // ---- gather a, b, c rows ----
        if (tid < 48) {
            const int which = tid >> 4, idx = tid & 15;
            const int row = (which == 0) ? gI[e] : (which == 1 ? gJ[e] : gK[e]);
            const float* src = (which == 0) ? A : (which == 1 ? Bm : Cm);
            sm[S_ABC + tid] = src[row * 16 + idx];
        }
        __syncthreads();

        // ---- BC outer product + WA contraction (W0 pre-contracted with a-pairs) ----
        sm[S_BC + tid] = sm[S_ABC + 16 + (tid >> 4)] * sm[S_ABC + 32 + (tid & 15)];
        {
            const float a0 = sm[S_ABC + 2 * wrp], a1 = sm[S_ABC + 2 * wrp + 1];
            ((float4*)(sm + S_WA))[wrp * 32 + lane] = make_float4(
                fmaf(w0r[0], a0, w0r[4] * a1),
                fmaf(w0r[1], a0, w0r[5] * a1),
                fmaf(w0r[2], a0, w0r[6] * a1),
                fmaf(w0r[3], a0, w0r[7] * a1));
        }
        __syncthreads();

        // ---- depth-first over the 8 layer-2 cells ----
#pragma unroll
        for (int q2 = 0; q2 < 8; ++q2) {
            const int d2 = (q2 >> 2) & 1, h2 = (q2 >> 1) & 1, w2b = q2 & 1;
            const int D1 = 2 * d2 + wd, H1 = 2 * h2 + wh, Wd1 = 2 * w2b + ww;

            // layer0: WA hoisted (reused by 8 taps), BC read as float4 blocks
            const float4 wa0 = ((const float4*)(sm + S_WA))[(2 * D1) * 32 + lane];
            const float4 wa1 = ((const float4*)(sm + S_WA))[(2 * D1 + 1) * 32 + lane];
#pragma unroll
            for (int qh = 0; qh < 2; ++qh) {
                const float4 bcA = *(const float4*)&sm[S_BC + (4 * H1 + 2 * qh) * 16 + 4 * Wd1];
                const float4 bcB = *(const float4*)&sm[S_BC + (4 * H1 + 2 * qh + 1) * 16 + 4 * Wd1];
                float v;
                v = fmaf(wa0.x, bcA.x, fmaf(wa0.y, bcA.y, fmaf(wa0.z, bcB.x, fmaf(wa0.w, bcB.y, bias0))));
                sm[S_Y0 + (wrp * 8 + qh * 2 + 0) * 32 + lane] = fmaxf(v, 0.f);
                v = fmaf(wa0.x, bcA.z, fmaf(wa0.y, bcA.w, fmaf(wa0.z, bcB.z, fmaf(wa0.w, bcB.w, bias0))));
                sm[S_Y0 + (wrp * 8 + qh * 2 + 1) * 32 + lane] = fmaxf(v, 0.f);
                v = fmaf(wa1.x, bcA.x, fmaf(wa1.y, bcA.y, fmaf(wa1.z, bcB.x, fmaf(wa1.w, bcB.y, bias0))));
                sm[S_Y0 + (wrp * 8 + 4 + qh * 2 + 0) * 32 + lane] = fmaxf(v, 0.f);
                v = fmaf(wa1.x, bcA.z, fmaf(wa1.y, bcA.w, fmaf(wa1.z, bcB.z, fmaf(wa1.w, bcB.w, bias0))));
                sm[S_Y0 + (wrp * 8 + 4 + qh * 2 + 1) * 32 + lane] = fmaxf(v, 0.f);
            }
            __syncthreads();

            // layer1 partials: warp's 4-channel slice, 8 positions
#pragma unroll
            for (int t1 = 0; t1 < 8; ++t1) {
                float accA = 0.f, accB = 0.f;
#pragma unroll
                for (int tap = 0; tap < 8; ++tap) {
                    const float4 v = *(const float4*)&sm[S_Y0 + (t1 * 8 + tap) * 32 + 4 * wrp];
                    accA = fmaf(w1r[tap],      v.x, accA);
                    accB = fmaf(w1r[8 + tap],  v.y, accB);
                    accA = fmaf(w1r[16 + tap], v.z, accA);
                    accB = fmaf(w1r[24 + tap], v.w, accB);
                }
                sm[S_P1 + (t1 * 8 + wrp) * 32 + lane] = accA + accB;
            }
            __syncthreads();

            // reduce -> y1
            {
                float s = sm[S_P1 + (wrp * 8 + 0) * 32 + lane];
#pragma unroll
                for (int wi = 1; wi < 8; ++wi) s += sm[S_P1 + (wrp * 8 + wi) * 32 + lane];
                sm[S_Y1 + wrp * 32 + lane] = fmaxf(s + bias1, 0.f);
            }
            __syncthreads();

            // layer2 partial for this q2 cell
            {
                float accA = 0.f, accB = 0.f;
#pragma unroll
                for (int t1 = 0; t1 < 8; ++t1) {
                    const float4 v = *(const float4*)&sm[S_Y1 + t1 * 32 + 4 * wrp];
                    accA = fmaf(w2r[t1],      v.x, accA);
                    accB = fmaf(w2r[8 + t1],  v.y, accB);
                    accA = fmaf(w2r[16 + t1], v.z, accA);
                    accB = fmaf(w2r[24 + t1], v.w, accB);
                }
                sm[S_P2 + (q2 * 8 + wrp) * 32 + lane] = accA + accB;
            }
        }
        __syncthreads();

        // reduce -> y2
        {
            float s = sm[S_P2 + (wrp * 8 + 0) * 32 + lane];
#pragma unroll
            for (int wi = 1; wi < 8; ++wi) s += sm[S_P2 + (wrp * 8 + wi) * 32 + lane];
            sm[S_Y2 + wrp * 32 + lane] = fmaxf(s + bias2, 0.f);
        }
        __syncthreads();

        // layer3 partial — W3 now register-resident
        {
            float accA = 0.f, accB = 0.f;
#pragma unroll
            for (int q2 = 0; q2 < 8; ++q2) {
                const float4 v = *(const float4*)&sm[S_Y2 + q2 * 32 + 4 * wrp];
                accA = fmaf(w3r[q2],      v.x, accA);
                accB = fmaf(w3r[8 + q2],  v.y, accB);
                accA = fmaf(w3r[16 + q2], v.z, accA);
                accB = fmaf(w3r[24 + q2], v.w, accB);
            }
            sm[S_P3 + wrp * 32 + lane] = accA + accB;
        }
        __syncthreads();

        // final reduce + fc + sigmoid
        if (wrp == 0) {
            float s = sm[S_P3 + lane];
#pragma unroll
            for (int wi = 1; wi < 8; ++wi) s += sm[S_P3 + wi * 32 + lane];
            const float y3 = fmaxf(s + bias3, 0.f);
            float v = fcw * y3;
#pragma unroll
            for (int off = 16; off; off >>= 1)
                v += __shfl_xor_sync(0xffffffffu, v, off);
            if (lane == 0)
                out[e] = 1.0f / (1.0f + __expf(-(v + fcb)));
        }
    }
}

extern "C" void kernel_launch(void* const* d_in, const int* in_sizes, int n_in,
                              void* d_out, int out_size) {
    const int*   gI  = (const int*)d_in[0];
    const int*   gJ  = (const int*)d_in[1];
    const int*   gK  = (const int*)d_in[2];
    const float* A   = (const float*)d_in[3];
    const float* B   = (const float*)d_in[4];
    const float* C   = (const float*)d_in[5];
    const float* W0  = (const float*)d_in[6];
    const float* b0  = (const float*)d_in[7];
    const float* W1  = (const float*)d_in[8];
    const float* b1  = (const float*)d_in[9];
    const float* W2  = (const float*)d_in[10];
    const float* b2  = (const float*)d_in[11];
    const float* W3  = (const float*)d_in[12];
    const float* b3  = (const float*)d_in[13];
    const float* FCW = (const float*)d_in[14];
    const float* FCB = (const float*)d_in[15];

    const int n = in_sizes[0];
    const int grid = (n + EPC - 1) / EPC;
    ntc_fused<<<grid, 256>>>(gI, gJ, gK, A, B, C, W0, b0, W1, b1, W2, b2,
                             W3, b3, FCW, FCB, (float*)d_out, n);
}

// round 4
// speedup vs baseline: 1.6573x; 1.0012x over previous
#include <cuda_runtime.h>

#define EPC 8
#define SMF 8448   // floats of shared: max(stage buffer 8446, persistent 8256)

// Persistent smem layout (float offsets); the weight-stage buffer overlays all of it
#define S_ABC 0      // 48
#define S_BC  64     // 16x16
#define S_WA  320    // 8x32 float4 (1024 floats)
#define S_Y0  1344   // [t1][tap][c] 8*8*32
#define S_P1  3392   // [t1][w][f]
#define S_Y1  5440   // [t1][c]
#define S_P2  5696   // [q2][w][f]
#define S_Y2  7744   // [q2][c]
#define S_P3  8000   // [w][f]

// Stage Wsrc (layout [f=32][c=32][t=8]) into transposed padded smem, fill per-thread regs
// wreg[cp*8+t] = Wsrc[(lane*32 + 4*wrp + cp)*8 + t]
#define STAGE(Wsrc, wreg) do {                                              \
    __syncthreads();                                                        \
    _Pragma("unroll")                                                       \
    for (int r = 0; r < 8; ++r) {                                           \
        int i4 = tid + 256 * r;                                             \
        float4 v = ((const float4*)(Wsrc))[i4];                             \
        int f = i4 >> 6, rem = i4 & 63, c = rem >> 1, tb = (rem & 1) * 4;   \
        sm[((tb + 0) * 32 + c) * 33 + f] = v.x;                             \
        sm[((tb + 1) * 32 + c) * 33 + f] = v.y;                             \
        sm[((tb + 2) * 32 + c) * 33 + f] = v.z;                             \
        sm[((tb + 3) * 32 + c) * 33 + f] = v.w;                             \
    }                                                                       \
    __syncthreads();                                                        \
    _Pragma("unroll")                                                       \
    for (int cp = 0; cp < 4; ++cp)                                          \
        _Pragma("unroll")                                                   \
        for (int t = 0; t < 8; ++t)                                         \
            wreg[cp * 8 + t] = sm[(t * 32 + 4 * wrp + cp) * 33 + lane];     \
} while (0)

__global__ __launch_bounds__(256, 2)
void ntc_fused(const int* __restrict__ gI, const int* __restrict__ gJ, const int* __restrict__ gK,
               const float* __restrict__ A, const float* __restrict__ Bm, const float* __restrict__ Cm,
               const float* __restrict__ W0, const float* __restrict__ b0,
               const float* __restrict__ W1, const float* __restrict__ b1,
               const float* __restrict__ W2, const float* __restrict__ b2,
               const float* __restrict__ W3, const float* __restrict__ b3,
               const float* __restrict__ FCW, const float* __restrict__ FCB,
               float* __restrict__ out, int n)
{
    __shared__ alignas(16) float sm[SMF];

    const int tid  = threadIdx.x;
    const int lane = tid & 31;
    const int wrp  = tid >> 5;

    // ---- CTA prologue: all conv weights into registers via staged transpose ----
    float w1r[32], w2r[32], w3r[32];
    STAGE(W1, w1r);
    STAGE(W2, w2r);
    STAGE(W3, w3r);

    float w0r[8];
#pragma unroll
    for (int t = 0; t < 8; ++t) w0r[t] = W0[lane * 8 + t];
    const float bias0 = b0[lane], bias1 = b1[lane], bias2 = b2[lane], bias3 = b3[lane];
    const float fcw = FCW[lane], fcb = FCB[0];

    const int wd = (wrp >> 2) & 1, wh = (wrp >> 1) & 1, ww = wrp & 1;

    const int ebase = blockIdx.x * EPC;
    for (int e0 = 0; e0 < EPC; ++e0) {
        const int e = ebase + e0;
        if (e >= n) break;             // uniform across CTA
        __syncthreads();               // smem reuse boundary (also covers prologue)

        // ---- gather a, b, c rows ----
        if (tid < 48) {
            const int which = tid >> 4, idx = tid & 15;
            const int row = (which == 0) ? gI[e] : (which == 1 ? gJ[e] : gK[e]);
            const float* src = (which == 0) ? A : (which == 1 ? Bm : Cm);
            sm[S_ABC + tid] = src[row * 16 + idx];
        }
        __syncthreads();

        // ---- BC outer product + WA contraction (W0 pre-contracted with a-pairs) ----
        sm[S_BC + tid] = sm[S_ABC + 16 + (tid >> 4)] * sm[S_ABC + 32 + (tid & 15)];
        {
            const float a0 = sm[S_ABC + 2 * wrp], a1 = sm[S_ABC + 2 * wrp + 1];
            ((float4*)(sm + S_WA))[wrp * 32 + lane] = make_float4(
                fmaf(w0r[0], a0, w0r[4] * a1),
                fmaf(w0r[1], a0, w0r[5] * a1),
                fmaf(w0r[2], a0, w0r[6] * a1),
                fmaf(w0r[3], a0, w0r[7] * a1));
        }
        __syncthreads();

        // ---- depth-first over the 8 layer-2 cells ----
#pragma unroll
        for (int q2 = 0; q2 < 8; ++q2) {
            const int d2 = (q2 >> 2) & 1, h2 = (q2 >> 1) & 1, w2b = q2 & 1;
            const int D1 = 2 * d2 + wd, H1 = 2 * h2 + wh, Wd1 = 2 * w2b + ww;

            // layer0: WA hoisted (reused by 8 taps), BC read as float4 blocks
            const float4 wa0 = ((const float4*)(sm + S_WA))[(2 * D1) * 32 + lane];
            const float4 wa1 = ((const float4*)(sm + S_WA))[(2 * D1 + 1) * 32 + lane];
#pragma unroll
            for (int qh = 0; qh < 2; ++qh) {
                const float4 bcA = *(const float4*)&sm[S_BC + (4 * H1 + 2 * qh) * 16 + 4 * Wd1];
                const float4 bcB = *(const float4*)&sm[S_BC + (4 * H1 + 2 * qh + 1) * 16 + 4 * Wd1];
                float v;
                v = fmaf(wa0.x, bcA.x, fmaf(wa0.y, bcA.y, fmaf(wa0.z, bcB.x, fmaf(wa0.w, bcB.y, bias0))));
                sm[S_Y0 + (wrp * 8 + qh * 2 + 0) * 32 + lane] = fmaxf(v, 0.f);
                v = fmaf(wa0.x, bcA.z, fmaf(wa0.y, bcA.w, fmaf(wa0.z, bcB.z, fmaf(wa0.w, bcB.w, bias0))));
                sm[S_Y0 + (wrp * 8 + qh * 2 + 1) * 32 + lane] = fmaxf(v, 0.f);
                v = fmaf(wa1.x, bcA.x, fmaf(wa1.y, bcA.y, fmaf(wa1.z, bcB.x, fmaf(wa1.w, bcB.y, bias0))));
                sm[S_Y0 + (wrp * 8 + 4 + qh * 2 + 0) * 32 + lane] = fmaxf(v, 0.f);
                v = fmaf(wa1.x, bcA.z, fmaf(wa1.y, bcA.w, fmaf(wa1.z, bcB.z, fmaf(wa1.w, bcB.w, bias0))));
                sm[S_Y0 + (wrp * 8 + 4 + qh * 2 + 1) * 32 + lane] = fmaxf(v, 0.f);
            }
            __syncthreads();

            // layer1 partials: warp's 4-channel slice, 8 positions
#pragma unroll
            for (int t1 = 0; t1 < 8; ++t1) {
                float accA = 0.f, accB = 0.f;
#pragma unroll
                for (int tap = 0; tap < 8; ++tap) {
                    const float4 v = *(const float4*)&sm[S_Y0 + (t1 * 8 + tap) * 32 + 4 * wrp];
                    accA = fmaf(w1r[tap],      v.x, accA);
                    accB = fmaf(w1r[8 + tap],  v.y, accB);
                    accA = fmaf(w1r[16 + tap], v.z, accA);
                    accB = fmaf(w1r[24 + tap], v.w, accB);
                }
                sm[S_P1 + (t1 * 8 + wrp) * 32 + lane] = accA + accB;
            }
            __syncthreads();

            // reduce -> y1
            {
                float s = sm[S_P1 + (wrp * 8 + 0) * 32 + lane];
#pragma unroll
                for (int wi = 1; wi < 8; ++wi) s += sm[S_P1 + (wrp * 8 + wi) * 32 + lane];
                sm[S_Y1 + wrp * 32 + lane] = fmaxf(s + bias1, 0.f);
            }
            __syncthreads();

            // layer2 partial for this q2 cell
            {
                float accA = 0.f, accB = 0.f;
#pragma unroll
                for (int t1 = 0; t1 < 8; ++t1) {
                    const float4 v = *(const float4*)&sm[S_Y1 + t1 * 32 + 4 * wrp];
                    accA = fmaf(w2r[t1],      v.x, accA);
                    accB = fmaf(w2r[8 + t1],  v.y, accB);
                    accA = fmaf(w2r[16 + t1], v.z, accA);
                    accB = fmaf(w2r[24 + t1], v.w, accB);
                }
                sm[S_P2 + (q2 * 8 + wrp) * 32 + lane] = accA + accB;
            }
        }
        __syncthreads();

        // reduce -> y2
        {
            float s = sm[S_P2 + (wrp * 8 + 0) * 32 + lane];
#pragma unroll
            for (int wi = 1; wi < 8; ++wi) s += sm[S_P2 + (wrp * 8 + wi) * 32 + lane];
            sm[S_Y2 + wrp * 32 + lane] = fmaxf(s + bias2, 0.f);
        }
        __syncthreads();

        // layer3 partial — W3 now register-resident
        {
            float accA = 0.f, accB = 0.f;
#pragma unroll
            for (int q2 = 0; q2 < 8; ++q2) {
                const float4 v = *(const float4*)&sm[S_Y2 + q2 * 32 + 4 * wrp];
                accA = fmaf(w3r[q2],      v.x, accA);
                accB = fmaf(w3r[8 + q2],  v.y, accB);
                accA = fmaf(w3r[16 + q2], v.z, accA);
                accB = fmaf(w3r[24 + q2], v.w, accB);
            }
            sm[S_P3 + wrp * 32 + lane] = accA + accB;
        }
        __syncthreads();

        // final reduce + fc + sigmoid
        if (wrp == 0) {
            float s = sm[S_P3 + lane];
#pragma unroll
            for (int wi = 1; wi < 8; ++wi) s += sm[S_P3 + wi * 32 + lane];
            const float y3 = fmaxf(s + bias3, 0.f);
            float v = fcw * y3;
#pragma unroll
            for (int off = 16; off; off >>= 1)
                v += __shfl_xor_sync(0xffffffffu, v, off);
            if (lane == 0)
                out[e] = 1.0f / (1.0f + __expf(-(v + fcb)));
        }
    }
}

extern "C" void kernel_launch(void* const* d_in, const int* in_sizes, int n_in,
                              void* d_out, int out_size) {
    const int*   gI  = (const int*)d_in[0];
    const int*   gJ  = (const int*)d_in[1];
    const int*   gK  = (const int*)d_in[2];
    const float* A   = (const float*)d_in[3];
    const float* B   = (const float*)d_in[4];
    const float* C   = (const float*)d_in[5];
    const float* W0  = (const float*)d_in[6];
    const float* b0  = (const float*)d_in[7];
    const float* W1  = (const float*)d_in[8];
    const float* b1  = (const float*)d_in[9];
    const float* W2  = (const float*)d_in[10];
    const float* b2  = (const float*)d_in[11];
    const float* W3  = (const float*)d_in[12];
    const float* b3  = (const float*)d_in[13];
    const float* FCW = (const float*)d_in[14];
    const float* FCB = (const float*)d_in[15];

    const int n = in_sizes[0];
    const int grid = (n + EPC - 1) / EPC;
    ntc_fused<<<grid, 256>>>(gI, gJ, gK, A, B, C, W0, b0, W1, b1, W2, b2,
                             W3, b3, FCW, FCB, (float*)d_out, n);
}